// round 7
// baseline (speedup 1.0000x reference)
#include <cuda_runtime.h>
#include <cstdint>

#define HID 128
#define K3  384
#define TM  64
#define NTHREADS 512

// Scratch (device globals: allocation-free rule).
// Levels alternate buffers by parity: level L stored in g_emb[L&1]; level 0 -> d_out.
__device__ float  g_emb0[33554432];          // max even level = 8: 262144*128
__device__ float  g_emb1[67108864];          // max odd  level = 9: 524288*128
__device__ float2 g_Wp[192 * 128];           // W_h pair-packed: Wp[p][j] = (W[j][2p], W[j][2p+1])

// Packed f32x2 FMA: d.lo += a.lo*b.lo ; d.hi += a.hi*b.hi   (sm_100+ PTX only)
__device__ __forceinline__ void ffma2(unsigned long long &d,
                                      unsigned long long a,
                                      unsigned long long b) {
    asm("fma.rn.f32x2 %0, %1, %2, %0;" : "+l"(d) : "l"(a), "l"(b));
}

// ---------------------------------------------------------------------------
// Pack W_h [128][384] into pair-major layout g_Wp[p][j], p = k/2.
// ---------------------------------------------------------------------------
__global__ void pack_w_kernel(const float* __restrict__ Wh) {
    int idx = blockIdx.x * blockDim.x + threadIdx.x;
    if (idx < 192 * 128) {
        int p = idx >> 7;
        int j = idx & 127;
        g_Wp[idx] = make_float2(Wh[j * K3 + 2 * p], Wh[j * K3 + 2 * p + 1]);
    }
}

// ---------------------------------------------------------------------------
// Leaf level (j=9): emb1 = relu(C9 @ Wu^T + bu).  8 rows/block, 256 threads.
// Memory-bound (writes 256MB).
// ---------------------------------------------------------------------------
__global__ void __launch_bounds__(256)
u_leaf_kernel(const float* __restrict__ contents,
              const float* __restrict__ Wu,
              const float* __restrict__ bu) {
    __shared__ float Wus[8][HID];   // transposed W_u
    int tid = threadIdx.x;
    for (int idx = tid; idx < HID * 8; idx += 256) {
        int c = idx >> 3, k = idx & 7;
        Wus[k][c] = Wu[idx];
    }
    __syncthreads();

    int lane = tid & 31;
    int row  = blockIdx.x * 8 + (tid >> 5);

    const float4* cp = (const float4*)(contents + (size_t)row * 8);
    float4 c0 = cp[0], c1 = cp[1];
    float cv[8] = {c0.x, c0.y, c0.z, c0.w, c1.x, c1.y, c1.z, c1.w};

    float4 b = *(const float4*)(bu + 4 * lane);
    float a0 = b.x, a1 = b.y, a2 = b.z, a3 = b.w;
    #pragma unroll
    for (int k = 0; k < 8; k++) {
        float4 w = *(const float4*)(&Wus[k][4 * lane]);
        a0 = fmaf(cv[k], w.x, a0);
        a1 = fmaf(cv[k], w.y, a1);
        a2 = fmaf(cv[k], w.z, a2);
        a3 = fmaf(cv[k], w.w, a3);
    }
    float4 o = make_float4(fmaxf(a0, 0.f), fmaxf(a1, 0.f),
                           fmaxf(a2, 0.f), fmaxf(a3, 0.f));
    *(float4*)(g_emb1 + (size_t)row * HID + 4 * lane) = o;
}

// ---------------------------------------------------------------------------
// Fused interior level:
//   u = relu(C @ Wu^T + bu)
//   H = [emb_prev[chL] | emb_prev[chR] | u]           (K = 384)
//   out = relu(H @ Wh^T + bh)
// One block = TM(=64) rows, 512 threads (16 warps, 4/SMSP for latency hiding).
// Warp tile: 4 rows x 128 cols; thread tile 4 rows x 4 cols (cols strided 32).
// K accumulated in packed f32x2 pairs (even/odd k in lo/hi halves).
// ---------------------------------------------------------------------------
#define HS_STRIDE 388                          // 64*388*4 = 99328 B, 16B-aligned rows
#define SMEM_HS_BYTES   (TM * HS_STRIDE * 4)   // 99328
#define SMEM_WS_OFF     SMEM_HS_BYTES
#define SMEM_WS_BYTES   (2 * 16 * 128 * 8)     // 32768 (double-buffered chunk)
#define SMEM_WUS_OFF    (SMEM_WS_OFF + SMEM_WS_BYTES)      // 132096
#define SMEM_CS_OFF     (SMEM_WUS_OFF + 8 * HID * 4)       // 136192
#define SMEM_TOTAL      (SMEM_CS_OFF + 8 * TM * 4)         // 138240

__global__ void __launch_bounds__(NTHREADS, 1)
fused_level_kernel(const float* __restrict__ contents,
                   const int*   __restrict__ children,
                   int prev_sel, int out_sel,
                   float* __restrict__ final_out,
                   const float* __restrict__ Wu,
                   const float* __restrict__ bu,
                   const float* __restrict__ bh) {
    extern __shared__ __align__(16) char smem[];
    float*  Hs  = (float*)smem;                       // [TM][HS_STRIDE]
    float2* Ws  = (float2*)(smem + SMEM_WS_OFF);      // [2][16][128]
    float*  Wus = (float*)(smem + SMEM_WUS_OFF);      // [8][128]
    float*  Cs  = (float*)(smem + SMEM_CS_OFF);       // [8][TM]

    const float* emb_prev = prev_sel ? g_emb1 : g_emb0;
    float* emb_out = (out_sel == 2) ? final_out : (out_sel ? g_emb1 : g_emb0);

    const int tid  = threadIdx.x;
    const int lane = tid & 31;
    const int warp = tid >> 5;
    const int row0 = blockIdx.x * TM;

    // --- Phase A: stage Wu (transposed), contents tile (transposed), gather H L/R
    for (int idx = tid; idx < HID * 8; idx += NTHREADS) {
        int c = idx >> 3, k = idx & 7;
        Wus[k * HID + c] = Wu[idx];
    }
    for (int idx = tid; idx < TM * 8; idx += NTHREADS) {
        float v = contents[row0 * 8 + idx];
        int r = idx >> 3, k = idx & 7;
        Cs[k * TM + r] = v;
    }
    for (int rr = warp; rr < TM; rr += 16) {
        int gL = children[2 * (row0 + rr)];
        int gR = children[2 * (row0 + rr) + 1];
        float4 vL = *(const float4*)(emb_prev + (size_t)gL * HID + 4 * lane);
        float4 vR = *(const float4*)(emb_prev + (size_t)gR * HID + 4 * lane);
        *(float4*)(Hs + rr * HS_STRIDE + 4 * lane)       = vL;
        *(float4*)(Hs + rr * HS_STRIDE + HID + 4 * lane) = vR;
    }
    __syncthreads();

    // --- Phase B: u -> Hs[:,256:384]; stage W chunk 0.
    // c-fast mapping: lane-consecutive Wus reads + Hs stores (conflict-free).
    for (int idx = tid; idx < TM * HID; idx += NTHREADS) {
        int c = idx & (HID - 1);
        int r = idx >> 7;
        float acc = bu[c];
        #pragma unroll
        for (int k = 0; k < 8; k++)
            acc = fmaf(Cs[k * TM + r], Wus[k * HID + c], acc);
        Hs[r * HS_STRIDE + 256 + c] = fmaxf(acc, 0.f);
    }
    for (int idx = tid; idx < 2048; idx += NTHREADS)
        Ws[idx] = g_Wp[idx];
    __syncthreads();

    // --- Phase C: main GEMM. 12 chunks of 32 k-values (16 pairs) each.
    const int rbase = warp * 4;                 // 16 warps x 4 rows = 64
    unsigned long long acc[4][4];
    #pragma unroll
    for (int i = 0; i < 4; i++)
        #pragma unroll
        for (int jj = 0; jj < 4; jj++) acc[i][jj] = 0ull;

    #pragma unroll 1
    for (int ch = 0; ch < 12; ch++) {
        const float2* Wcur = Ws + (ch & 1) * 2048;

        float2 pf[4];
        if (ch < 11) {
            #pragma unroll
            for (int t = 0; t < 4; t++)
                pf[t] = g_Wp[(ch + 1) * 2048 + tid + t * NTHREADS];
        }

        #pragma unroll
        for (int k4 = 0; k4 < 32; k4 += 4) {
            // a[i]: packed pairs (k,k+1),(k+2,k+3) for row rbase+i — warp-broadcast LDS.128
            ulonglong2 a[4];
            #pragma unroll
            for (int i = 0; i < 4; i++)
                a[i] = *(const ulonglong2*)(Hs + (rbase + i) * HS_STRIDE + ch * 32 + k4);
            #pragma unroll
            for (int jj = 0; jj < 4; jj++) {
                int j = lane + 32 * jj;          // strided cols: conflict-free w loads
                unsigned long long w0 = *(const unsigned long long*)(Wcur + (k4 >> 1) * 128 + j);
                unsigned long long w1 = *(const unsigned long long*)(Wcur + ((k4 >> 1) + 1) * 128 + j);
                #pragma unroll
                for (int i = 0; i < 4; i++) {
                    ffma2(acc[i][jj], a[i].x, w0);
                    ffma2(acc[i][jj], a[i].y, w1);
                }
            }
        }

        if (ch < 11) {
            float2* Wnxt = Ws + ((ch + 1) & 1) * 2048;
            #pragma unroll
            for (int t = 0; t < 4; t++)
                Wnxt[tid + t * NTHREADS] = pf[t];
        }
        __syncthreads();
    }

    // --- Epilogue: reduce packed halves, add bias, relu, store
    #pragma unroll
    for (int jj = 0; jj < 4; jj++) {
        int j = lane + 32 * jj;
        float bias = bh[j];
        #pragma unroll
        for (int i = 0; i < 4; i++) {
            unsigned int lo = (unsigned int)(acc[i][jj] & 0xffffffffull);
            unsigned int hi = (unsigned int)(acc[i][jj] >> 32);
            float v = __uint_as_float(lo) + __uint_as_float(hi) + bias;
            emb_out[(size_t)(row0 + rbase + i) * HID + j] = fmaxf(v, 0.f);
        }
    }
}

// ---------------------------------------------------------------------------
// Launch.
// Input order (metadata): contents_0..9 [0..9], children_0..8 [10..18],
//                         W_u [19], b_u [20], W_h [21], b_h [22]
// Output: [1024,128] float
// ---------------------------------------------------------------------------
extern "C" void kernel_launch(void* const* d_in, const int* in_sizes, int n_in,
                              void* d_out, int out_size) {
    const float* Wu = (const float*)d_in[19];
    const float* bu = (const float*)d_in[20];
    const float* Wh = (const float*)d_in[21];
    const float* bh = (const float*)d_in[22];
    float* out = (float*)d_out;

    cudaFuncSetAttribute(fused_level_kernel,
                         cudaFuncAttributeMaxDynamicSharedMemorySize, SMEM_TOTAL);

    pack_w_kernel<<<96, 256>>>(Wh);

    // level 9: 524288 rows, 8 rows/block
    u_leaf_kernel<<<65536, 256>>>((const float*)d_in[9], Wu, bu);

    for (int j = 8; j >= 0; --j) {
        int n = 1024 << j;
        int prev_sel = (j + 1) & 1;                 // storage parity of level j+1
        int out_sel  = (j == 0) ? 2 : (j & 1);      // 2 => write d_out
        fused_level_kernel<<<n / TM, NTHREADS, SMEM_TOTAL>>>(
            (const float*)d_in[j], (const int*)d_in[10 + j],
            prev_sel, out_sel, out, Wu, bu, bh);
    }
}

// round 17
// speedup vs baseline: 1.0261x; 1.0261x over previous
#include <cuda_runtime.h>
#include <cstdint>

#define HID 128
#define K3  384
#define NTHREADS 512

// Scratch (device globals: allocation-free rule).
// Levels alternate buffers by parity: level L stored in g_emb[L&1]; level 0 -> d_out.
__device__ float  g_emb0[33554432];          // max even level = 8: 262144*128
__device__ float  g_emb1[67108864];          // max odd  level = 9: 524288*128
__device__ float2 g_Wp[192 * 128];           // W_h pair-packed: Wp[p][j] = (W[j][2p], W[j][2p+1])

// Packed f32x2 FMA: d.lo += a.lo*b.lo ; d.hi += a.hi*b.hi   (sm_100+ PTX only)
__device__ __forceinline__ void ffma2(unsigned long long &d,
                                      unsigned long long a,
                                      unsigned long long b) {
    asm("fma.rn.f32x2 %0, %1, %2, %0;" : "+l"(d) : "l"(a), "l"(b));
}

__device__ __forceinline__ void cp_async16(void* sptr, const void* gptr) {
    unsigned s = (unsigned)__cvta_generic_to_shared(sptr);
    asm volatile("cp.async.cg.shared.global [%0], [%1], 16;" :: "r"(s), "l"(gptr));
}
#define CP_COMMIT()  asm volatile("cp.async.commit_group;" ::)
#define CP_WAIT(n)   asm volatile("cp.async.wait_group %0;" :: "n"(n))

// ---------------------------------------------------------------------------
// Pack W_h [128][384] into pair-major layout g_Wp[p][j], p = k/2.
// ---------------------------------------------------------------------------
__global__ void pack_w_kernel(const float* __restrict__ Wh) {
    int idx = blockIdx.x * blockDim.x + threadIdx.x;
    if (idx < 192 * 128) {
        int p = idx >> 7;
        int j = idx & 127;
        g_Wp[idx] = make_float2(Wh[j * K3 + 2 * p], Wh[j * K3 + 2 * p + 1]);
    }
}

// ---------------------------------------------------------------------------
// Leaf level (j=9): emb1 = relu(C9 @ Wu^T + bu).  8 rows/block, 256 threads.
// Memory-bound (writes 256MB).
// ---------------------------------------------------------------------------
__global__ void __launch_bounds__(256)
u_leaf_kernel(const float* __restrict__ contents,
              const float* __restrict__ Wu,
              const float* __restrict__ bu) {
    __shared__ float Wus[8][HID];
    int tid = threadIdx.x;
    for (int idx = tid; idx < HID * 8; idx += 256) {
        int c = idx >> 3, k = idx & 7;
        Wus[k][c] = Wu[idx];
    }
    __syncthreads();

    int lane = tid & 31;
    int row  = blockIdx.x * 8 + (tid >> 5);

    const float4* cp = (const float4*)(contents + (size_t)row * 8);
    float4 c0 = cp[0], c1 = cp[1];
    float cv[8] = {c0.x, c0.y, c0.z, c0.w, c1.x, c1.y, c1.z, c1.w};

    float4 b = *(const float4*)(bu + 4 * lane);
    float a0 = b.x, a1 = b.y, a2 = b.z, a3 = b.w;
    #pragma unroll
    for (int k = 0; k < 8; k++) {
        float4 w = *(const float4*)(&Wus[k][4 * lane]);
        a0 = fmaf(cv[k], w.x, a0);
        a1 = fmaf(cv[k], w.y, a1);
        a2 = fmaf(cv[k], w.z, a2);
        a3 = fmaf(cv[k], w.w, a3);
    }
    float4 o = make_float4(fmaxf(a0, 0.f), fmaxf(a1, 0.f),
                           fmaxf(a2, 0.f), fmaxf(a3, 0.f));
    *(float4*)(g_emb1 + (size_t)row * HID + 4 * lane) = o;
}

// ---------------------------------------------------------------------------
// Fused interior level, templated on tile height.
//   u = relu(C @ Wu^T + bu) ; H = [embL | embR | u] (K=384) ; out = relu(H Wh^T + bh)
// 512 threads = 16 warps, R = TM/16 rows per warp, 4 cols/thread (strided 32).
// W streamed from L2 via cp.async in double-buffered 16-k (8KB) chunks.
// ---------------------------------------------------------------------------
#define NCH 24           // 384 / 16
#define CHUNK_F2 1024    // 8 pairs * 128 cols per chunk

template<int TM, int R>
__global__ void __launch_bounds__(NTHREADS, 1)
fused_level_kernel(const float* __restrict__ contents,
                   const int*   __restrict__ children,
                   int prev_sel, int out_sel,
                   float* __restrict__ final_out,
                   const float* __restrict__ Wu,
                   const float* __restrict__ bu,
                   const float* __restrict__ bh) {
    constexpr int HS_BYTES  = TM * K3 * 4;            // Hs [TM][384]
    constexpr int WS_OFF    = HS_BYTES;               // Ws [2][8][128] float2
    constexpr int WUS_OFF   = WS_OFF + 2 * CHUNK_F2 * 8;
    constexpr int CS_OFF    = WUS_OFF + 8 * HID * 4;  // Cs [8][TM]

    extern __shared__ __align__(16) char smem[];
    float*  Hs  = (float*)smem;
    float2* Ws  = (float2*)(smem + WS_OFF);
    float*  Wus = (float*)(smem + WUS_OFF);
    float*  Cs  = (float*)(smem + CS_OFF);

    const float* emb_prev = prev_sel ? g_emb1 : g_emb0;
    float* emb_out = (out_sel == 2) ? final_out : (out_sel ? g_emb1 : g_emb0);

    const int tid  = threadIdx.x;
    const int lane = tid & 31;
    const int warp = tid >> 5;
    const int row0 = blockIdx.x * TM;

    // Kick off W chunk 0 immediately (overlaps phases A/B).
    cp_async16(&Ws[tid * 2], &g_Wp[tid * 2]);
    CP_COMMIT();

    // --- Phase A: stage Wu (transposed), contents (transposed), gather child rows
    for (int idx = tid; idx < HID * 8; idx += NTHREADS) {
        int c = idx >> 3, k = idx & 7;
        Wus[k * HID + c] = Wu[idx];
    }
    for (int idx = tid; idx < TM * 8; idx += NTHREADS) {
        float v = contents[row0 * 8 + idx];
        int r = idx >> 3, k = idx & 7;
        Cs[k * TM + r] = v;
    }
    for (int rr = warp; rr < TM; rr += 16) {
        int gL = children[2 * (row0 + rr)];
        int gR = children[2 * (row0 + rr) + 1];
        float4 vL = *(const float4*)(emb_prev + (size_t)gL * HID + 4 * lane);
        float4 vR = *(const float4*)(emb_prev + (size_t)gR * HID + 4 * lane);
        *(float4*)(Hs + rr * K3 + 4 * lane)       = vL;
        *(float4*)(Hs + rr * K3 + HID + 4 * lane) = vR;
    }
    __syncthreads();

    // --- Phase B: u -> Hs[:,256:384].  c-fast: conflict-free reads and stores.
    for (int idx = tid; idx < TM * HID; idx += NTHREADS) {
        int c = idx & (HID - 1);
        int r = idx >> 7;
        float acc = bu[c];
        #pragma unroll
        for (int k = 0; k < 8; k++)
            acc = fmaf(Cs[k * TM + r], Wus[k * HID + c], acc);
        Hs[r * K3 + 256 + c] = fmaxf(acc, 0.f);
    }

    // --- Phase C: main GEMM, 24 chunks of 16 k (8 pairs), cp.async double-buffered.
    const int rbase = warp * R;
    unsigned long long acc[R][4];
    #pragma unroll
    for (int i = 0; i < R; i++)
        #pragma unroll
        for (int jj = 0; jj < 4; jj++) acc[i][jj] = 0ull;

    #pragma unroll 1
    for (int ch = 0; ch < NCH; ch++) {
        if (ch < NCH - 1) {
            cp_async16(&Ws[((ch + 1) & 1) * CHUNK_F2 + tid * 2],
                       &g_Wp[(ch + 1) * CHUNK_F2 + tid * 2]);
            CP_COMMIT();
            CP_WAIT(1);
        } else {
            CP_WAIT(0);
        }
        __syncthreads();   // chunk ch visible to all; Hs ready (first iter)

        const float2* Wcur = Ws + (ch & 1) * CHUNK_F2;

        #pragma unroll
        for (int k4 = 0; k4 < 16; k4 += 4) {
            ulonglong2 a[R];                           // pairs (k,k+1),(k+2,k+3) per row
            #pragma unroll
            for (int i = 0; i < R; i++)
                a[i] = *(const ulonglong2*)(Hs + (rbase + i) * K3 + ch * 16 + k4);
            #pragma unroll
            for (int jj = 0; jj < 4; jj++) {
                int j = lane + 32 * jj;
                unsigned long long w0 = *(const unsigned long long*)(Wcur + (k4 >> 1) * 128 + j);
                unsigned long long w1 = *(const unsigned long long*)(Wcur + ((k4 >> 1) + 1) * 128 + j);
                #pragma unroll
                for (int i = 0; i < R; i++) {
                    ffma2(acc[i][jj], a[i].x, w0);
                    ffma2(acc[i][jj], a[i].y, w1);
                }
            }
        }
        __syncthreads();   // compute done before buffer (ch&1) is overwritten at ch+2
    }

    // --- Epilogue: reduce packed halves, add bias, relu, store (coalesced)
    #pragma unroll
    for (int jj = 0; jj < 4; jj++) {
        int j = lane + 32 * jj;
        float bias = bh[j];
        #pragma unroll
        for (int i = 0; i < R; i++) {
            unsigned int lo = (unsigned int)(acc[i][jj] & 0xffffffffull);
            unsigned int hi = (unsigned int)(acc[i][jj] >> 32);
            float v = __uint_as_float(lo) + __uint_as_float(hi) + bias;
            emb_out[(size_t)(row0 + rbase + i) * HID + j] = fmaxf(v, 0.f);
        }
    }
}

// ---------------------------------------------------------------------------
// Launch.  Inputs: contents_0..9 [0..9], children_0..8 [10..18],
//                  W_u [19], b_u [20], W_h [21], b_h [22].  Output [1024,128] f32.
// ---------------------------------------------------------------------------
#define SMEM_128 (128 * K3 * 4 + 2 * CHUNK_F2 * 8 + 8 * HID * 4 + 8 * 128 * 4)  // 221184
#define SMEM_32  (32  * K3 * 4 + 2 * CHUNK_F2 * 8 + 8 * HID * 4 + 8 * 32  * 4)  // 70656

extern "C" void kernel_launch(void* const* d_in, const int* in_sizes, int n_in,
                              void* d_out, int out_size) {
    const float* Wu = (const float*)d_in[19];
    const float* bu = (const float*)d_in[20];
    const float* Wh = (const float*)d_in[21];
    const float* bh = (const float*)d_in[22];
    float* out = (float*)d_out;

    cudaFuncSetAttribute(fused_level_kernel<128, 8>,
                         cudaFuncAttributeMaxDynamicSharedMemorySize, SMEM_128);
    cudaFuncSetAttribute(fused_level_kernel<32, 2>,
                         cudaFuncAttributeMaxDynamicSharedMemorySize, SMEM_32);

    pack_w_kernel<<<96, 256>>>(Wh);

    // level 9: 524288 rows, 8 rows/block
    u_leaf_kernel<<<65536, 256>>>((const float*)d_in[9], Wu, bu);

    for (int j = 8; j >= 0; --j) {
        int n = 1024 << j;
        int prev_sel = (j + 1) & 1;                 // storage parity of level j+1
        int out_sel  = (j == 0) ? 2 : (j & 1);      // 2 => write d_out
        if (j >= 5) {
            fused_level_kernel<128, 8><<<n / 128, NTHREADS, SMEM_128>>>(
                (const float*)d_in[j], (const int*)d_in[10 + j],
                prev_sel, out_sel, out, Wu, bu, bh);
        } else {
            fused_level_kernel<32, 2><<<n / 32, NTHREADS, SMEM_32>>>(
                (const float*)d_in[j], (const int*)d_in[10 + j],
                prev_sel, out_sel, out, Wu, bu, bh);
        }
    }
}